// round 1
// baseline (speedup 1.0000x reference)
#include <cuda_runtime.h>
#include <math.h>

#define N_TOK 32768
#define K_CB  1024
#define D_DIM 256
#define HW    1024
#define CHW   (256*1024)

#define TM 128
#define TN 64
#define SMEM_X (D_DIM*TM)   // floats
#define SMEM_W (D_DIM*TN)   // floats
#define SMEM_FLOATS (SMEM_X + SMEM_W + TM)
#define SMEM_BYTES (SMEM_FLOATS * 4)

// ---- scratch (device globals; no allocation allowed) ----
__device__ float  g_wt[D_DIM * K_CB];   // transposed codebook Wt[d][k]
__device__ float  g_wsq[K_CB];          // ||w_k||^2
__device__ int    g_idx[N_TOK];         // winning code per token
__device__ int    g_cnt[K_CB];          // histogram
__device__ double g_loss;               // sum of ||x - w_idx||^2

// ============================================================
// prep: transpose W, compute ||w||^2, zero histogram/loss
// ============================================================
__global__ void prep_kernel(const float* __restrict__ w) {
    int k = blockIdx.x;
    int d = threadIdx.x;
    float v = w[k * D_DIM + d];
    g_wt[d * K_CB + k] = v;

    float s = v * v;
    __shared__ float red[8];
    #pragma unroll
    for (int o = 16; o; o >>= 1) s += __shfl_xor_sync(0xffffffffu, s, o);
    if ((d & 31) == 0) red[d >> 5] = s;
    __syncthreads();
    if (d == 0) {
        float t = 0.f;
        #pragma unroll
        for (int i = 0; i < 8; i++) t += red[i];
        g_wsq[k] = t;
    }
    if (blockIdx.x == 0) {
        for (int i = d; i < K_CB; i += blockDim.x) g_cnt[i] = 0;
        if (d == 0) g_loss = 0.0;
    }
}

// ============================================================
// main: fused fp32 GEMM + argmin over codebook
//   block: 256 threads = 16(ty, tokens) x 16(tx, codes)
//   tile : TM=128 tokens x TN=64 codes per chunk, 16 chunks
// ============================================================
extern __shared__ float smem[];
__global__ void __launch_bounds__(256, 1) vq_main_kernel(const float* __restrict__ x) {
    float* Xs   = smem;                    // [d][m], stride TM
    float* Ws   = smem + SMEM_X;           // [d][kk], stride TN
    float* sxsq = smem + SMEM_X + SMEM_W;  // [TM] token ||x||^2
    __shared__ float s_loss;

    const int tid = threadIdx.x;
    const int tx = tid & 15, ty = tid >> 4;
    const int n0 = blockIdx.x * TM;

    if (tid < TM) sxsq[tid] = 0.f;
    if (tid == 0) s_loss = 0.f;
    __syncthreads();

    // ---- load X tile: x_flat[n][d] = inputs[b, d, hw]; coalesced over m ----
    {
        const int m = tid & 127;
        const int dbase = tid >> 7;  // 0 or 1
        const int n = n0 + m;
        const int b = n >> 10, hw = n & 1023;
        const float* px = x + (size_t)b * CHW + hw;
        float xs = 0.f;
        #pragma unroll 8
        for (int it = 0; it < 128; ++it) {
            int d = dbase + 2 * it;
            float v = px[(size_t)d * HW];
            Xs[d * TM + m] = v;
            xs += v * v;
        }
        atomicAdd(&sxsq[m], xs);
    }

    float bestv[8];
    int   besti[8];
    #pragma unroll
    for (int i = 0; i < 8; i++) { bestv[i] = 3.4e38f; besti[i] = 0; }

    for (int c = 0; c < K_CB / TN; ++c) {
        const int k0 = c * TN;
        __syncthreads();  // previous chunk's Ws consumers done
        // ---- load W chunk from transposed table: coalesced, conflict-free ----
        {
            const int kk4 = (tid & 15) * 4;
            const int drow = tid >> 4;
            #pragma unroll
            for (int it = 0; it < 16; ++it) {
                int d = drow + it * 16;
                float4 v = *(const float4*)&g_wt[(size_t)d * K_CB + k0 + kk4];
                *(float4*)&Ws[d * TN + kk4] = v;
            }
        }
        __syncthreads();

        float acc[8][4];
        #pragma unroll
        for (int i = 0; i < 8; i++)
            #pragma unroll
            for (int j = 0; j < 4; j++) acc[i][j] = 0.f;

        #pragma unroll 4
        for (int d = 0; d < D_DIM; ++d) {
            float4 wv = *(const float4*)&Ws[d * TN + tx * 4];
            float4 x0 = *(const float4*)&Xs[d * TM + ty * 8];
            float4 x1 = *(const float4*)&Xs[d * TM + ty * 8 + 4];
            float xr[8] = {x0.x, x0.y, x0.z, x0.w, x1.x, x1.y, x1.z, x1.w};
            float wr[4] = {wv.x, wv.y, wv.z, wv.w};
            #pragma unroll
            for (int i = 0; i < 8; i++)
                #pragma unroll
                for (int j = 0; j < 4; j++)
                    acc[i][j] = fmaf(xr[i], wr[j], acc[i][j]);
        }

        // ---- epilogue: score = ||w||^2 - 2 x.w ; running argmin ----
        #pragma unroll
        for (int j = 0; j < 4; j++) {
            int k = k0 + tx * 4 + j;
            float wsq = g_wsq[k];
            #pragma unroll
            for (int i = 0; i < 8; i++) {
                float s = fmaf(-2.f, acc[i][j], wsq);
                if (s < bestv[i]) { bestv[i] = s; besti[i] = k; }
            }
        }
    }

    // ---- reduce argmin across the 16 tx lanes (same-ty group within warp) ----
    #pragma unroll
    for (int off = 8; off; off >>= 1) {
        #pragma unroll
        for (int i = 0; i < 8; i++) {
            float ov = __shfl_xor_sync(0xffffffffu, bestv[i], off);
            int   oi = __shfl_xor_sync(0xffffffffu, besti[i], off);
            if (ov < bestv[i] || (ov == bestv[i] && oi < besti[i])) {
                bestv[i] = ov; besti[i] = oi;
            }
        }
    }

    if (tx == 0) {
        float lsum = 0.f;
        #pragma unroll
        for (int i = 0; i < 8; i++) {
            int m = ty * 8 + i;
            int n = n0 + m;
            g_idx[n] = besti[i];
            atomicAdd(&g_cnt[besti[i]], 1);
            lsum += sxsq[m] + bestv[i];   // ||x||^2 + (||w||^2 - 2 x.w)
        }
        atomicAdd(&s_loss, lsum);
    }
    __syncthreads();
    if (tid == 0) atomicAdd(&g_loss, (double)s_loss);
}

// ============================================================
// out: gather codebook rows back to BCHW, float4 per thread
// ============================================================
__global__ void out_kernel(const float* __restrict__ w, float* __restrict__ out) {
    int i = blockIdx.x * blockDim.x + threadIdx.x;  // over 8388608/4
    int hw = i & 1023;
    int c4 = (i >> 10) & 63;
    int b  = i >> 16;
    int n  = (b << 10) | hw;
    int idx = g_idx[n];
    float4 v = *(const float4*)&w[(size_t)idx * D_DIM + c4 * 4];
    size_t base = (size_t)b * CHW + (size_t)(c4 * 4) * HW + hw;
    out[base]            = v.x;
    out[base + HW]       = v.y;
    out[base + 2 * HW]   = v.z;
    out[base + 3 * HW]   = v.w;
}

// ============================================================
// one-hot scatter (region pre-zeroed by memset)
// ============================================================
__global__ void scat_kernel(float* __restrict__ enc) {
    int n = blockIdx.x * blockDim.x + threadIdx.x;
    enc[(size_t)n * K_CB + g_idx[n]] = 1.0f;
}

// ============================================================
// finalize: loss + entropy scalars
// ============================================================
__global__ void fin_kernel(float* __restrict__ scal) {
    __shared__ float red[32];
    int k = threadIdx.x;
    float p = (float)g_cnt[k] / (float)N_TOK;
    float t = -p * logf(p + 1e-10f);
    #pragma unroll
    for (int o = 16; o; o >>= 1) t += __shfl_xor_sync(0xffffffffu, t, o);
    if ((k & 31) == 0) red[k >> 5] = t;
    __syncthreads();
    if (k == 0) {
        float e = 0.f;
        #pragma unroll
        for (int i = 0; i < 32; i++) e += red[i];
        double mean = g_loss / ((double)N_TOK * (double)D_DIM);
        scal[0] = (float)(0.25 * mean);
        scal[1] = e;
    }
}

// ============================================================
extern "C" void kernel_launch(void* const* d_in, const int* in_sizes, int n_in,
                              void* d_out, int out_size) {
    const float* x = (const float*)d_in[0];   // [32,256,32,32]
    const float* w = (const float*)d_in[1];   // [1024,256]
    float* out = (float*)d_out;

    // layout: out (8388608) | loss (1) | entropy (1) | encodings (33554432)
    size_t enc_off  = (size_t)out_size - (size_t)N_TOK * K_CB;
    size_t scal_off = enc_off - 2;
    float* scal = out + scal_off;
    float* enc  = out + enc_off;

    cudaFuncSetAttribute(vq_main_kernel,
                         cudaFuncAttributeMaxDynamicSharedMemorySize, SMEM_BYTES);

    prep_kernel<<<K_CB, D_DIM>>>(w);
    cudaMemsetAsync(enc, 0, (size_t)N_TOK * K_CB * sizeof(float));
    vq_main_kernel<<<N_TOK / TM, 256, SMEM_BYTES>>>(x);
    out_kernel<<<(8388608 / 4) / 256, 256>>>(w, out);
    scat_kernel<<<N_TOK / 256, 256>>>(enc);
    fin_kernel<<<1, K_CB>>>(scal);
}

// round 2
// speedup vs baseline: 1.1528x; 1.1528x over previous
#include <cuda_runtime.h>
#include <math.h>

#define N_TOK 32768
#define K_CB  1024
#define D_DIM 256
#define HW    1024
#define CHW   (256*1024)

#define TM 128
#define TN 64
#define SMEM_X (D_DIM*TM)   // floats
#define SMEM_W (D_DIM*TN)   // floats
#define SMEM_FLOATS (SMEM_X + SMEM_W + TM)
#define SMEM_BYTES (SMEM_FLOATS * 4)

// packed fp32x2 FMA (Blackwell): two IEEE fp32 FMAs per instruction
#define FMA2(dst, a, b, c) \
    asm("fma.rn.f32x2 %0, %1, %2, %3;" : "=l"(dst) : "l"(a), "l"(b), "l"(c))
#define PACK2(dst, lo, hi) \
    asm("mov.b64 %0, {%1, %2};" : "=l"(dst) : "r"(lo), "r"(hi))

// ---- scratch (device globals; no allocation allowed) ----
__device__ float  g_wt[D_DIM * K_CB];   // transposed codebook Wt[d][k]
__device__ float  g_wsq[K_CB];          // ||w_k||^2
__device__ int    g_idx[N_TOK];         // winning code per token
__device__ int    g_cnt[K_CB];          // histogram
__device__ double g_loss;               // sum of ||x - w_idx||^2

// ============================================================
// prep: transpose W, compute ||w||^2, zero histogram/loss
// ============================================================
__global__ void prep_kernel(const float* __restrict__ w) {
    int k = blockIdx.x;
    int d = threadIdx.x;
    float v = w[k * D_DIM + d];
    g_wt[d * K_CB + k] = v;

    float s = v * v;
    __shared__ float red[8];
    #pragma unroll
    for (int o = 16; o; o >>= 1) s += __shfl_xor_sync(0xffffffffu, s, o);
    if ((d & 31) == 0) red[d >> 5] = s;
    __syncthreads();
    if (d == 0) {
        float t = 0.f;
        #pragma unroll
        for (int i = 0; i < 8; i++) t += red[i];
        g_wsq[k] = t;
    }
    if (blockIdx.x == 0) {
        for (int i = d; i < K_CB; i += blockDim.x) g_cnt[i] = 0;
        if (d == 0) g_loss = 0.0;
    }
}

// ============================================================
// main: fused fp32 GEMM + argmin, f32x2-packed inner loop
//   block: 256 threads = 16(ty, tokens) x 16(tx, codes)
//   tile : TM=128 tokens x TN=64 codes per chunk, 16 chunks
//   accumulators: 4 token-pairs x 4 codes, packed f32x2
// ============================================================
extern __shared__ float smem[];
__global__ void __launch_bounds__(256, 1) vq_main_kernel(const float* __restrict__ x) {
    float* Xs   = smem;                    // [d][m], stride TM
    float* Ws   = smem + SMEM_X;           // [d][kk], stride TN
    float* sxsq = smem + SMEM_X + SMEM_W;  // [TM] token ||x||^2
    __shared__ float s_loss;

    const int tid = threadIdx.x;
    const int tx = tid & 15, ty = tid >> 4;
    const int n0 = blockIdx.x * TM;

    if (tid < TM) sxsq[tid] = 0.f;
    if (tid == 0) s_loss = 0.f;
    __syncthreads();

    // ---- load X tile: x_flat[n][d] = inputs[b, d, hw]; coalesced over m ----
    {
        const int m = tid & 127;
        const int dbase = tid >> 7;  // 0 or 1
        const int n = n0 + m;
        const int b = n >> 10, hw = n & 1023;
        const float* px = x + (size_t)b * CHW + hw;
        float xs = 0.f;
        #pragma unroll 8
        for (int it = 0; it < 128; ++it) {
            int d = dbase + 2 * it;
            float v = px[(size_t)d * HW];
            Xs[d * TM + m] = v;
            xs += v * v;
        }
        atomicAdd(&sxsq[m], xs);
    }

    float bestv[8];
    int   besti[8];
    #pragma unroll
    for (int i = 0; i < 8; i++) { bestv[i] = 3.4e38f; besti[i] = 0; }

    for (int c = 0; c < K_CB / TN; ++c) {
        const int k0 = c * TN;
        __syncthreads();  // previous chunk's Ws consumers done
        // ---- load W chunk from transposed table: coalesced, conflict-free ----
        {
            const int kk4 = (tid & 15) * 4;
            const int drow = tid >> 4;
            #pragma unroll
            for (int it = 0; it < 16; ++it) {
                int d = drow + it * 16;
                float4 v = *(const float4*)&g_wt[(size_t)d * K_CB + k0 + kk4];
                *(float4*)&Ws[d * TN + kk4] = v;
            }
        }
        __syncthreads();

        // packed accumulators: acc2[i2][j] holds tokens (ty*8+2*i2, +1), code tx*4+j
        unsigned long long acc2[4][4];
        #pragma unroll
        for (int i = 0; i < 4; i++)
            #pragma unroll
            for (int j = 0; j < 4; j++) acc2[i][j] = 0ull;

        #pragma unroll 4
        for (int d = 0; d < D_DIM; ++d) {
            float4 wv = *(const float4*)&Ws[d * TN + tx * 4];
            unsigned long long w2[4];
            PACK2(w2[0], __float_as_uint(wv.x), __float_as_uint(wv.x));
            PACK2(w2[1], __float_as_uint(wv.y), __float_as_uint(wv.y));
            PACK2(w2[2], __float_as_uint(wv.z), __float_as_uint(wv.z));
            PACK2(w2[3], __float_as_uint(wv.w), __float_as_uint(wv.w));

            ulonglong2 xa = *(const ulonglong2*)&Xs[d * TM + ty * 8];      // m0..m3
            ulonglong2 xb = *(const ulonglong2*)&Xs[d * TM + ty * 8 + 4];  // m4..m7
            unsigned long long x2[4] = {xa.x, xa.y, xb.x, xb.y};

            #pragma unroll
            for (int i = 0; i < 4; i++)
                #pragma unroll
                for (int j = 0; j < 4; j++)
                    FMA2(acc2[i][j], x2[i], w2[j], acc2[i][j]);
        }

        // ---- epilogue: score = ||w||^2 - 2 x.w ; running argmin ----
        #pragma unroll
        for (int j = 0; j < 4; j++) {
            int k = k0 + tx * 4 + j;
            float wsq = g_wsq[k];
            #pragma unroll
            for (int i2 = 0; i2 < 4; i2++) {
                float dlo = __uint_as_float((unsigned int)acc2[i2][j]);
                float dhi = __uint_as_float((unsigned int)(acc2[i2][j] >> 32));
                float slo = fmaf(-2.f, dlo, wsq);
                float shi = fmaf(-2.f, dhi, wsq);
                int ilo = i2 * 2, ihi = ilo + 1;
                if (slo < bestv[ilo]) { bestv[ilo] = slo; besti[ilo] = k; }
                if (shi < bestv[ihi]) { bestv[ihi] = shi; besti[ihi] = k; }
            }
        }
    }

    // ---- reduce argmin across the 16 tx lanes (same-ty group within warp) ----
    #pragma unroll
    for (int off = 8; off; off >>= 1) {
        #pragma unroll
        for (int i = 0; i < 8; i++) {
            float ov = __shfl_xor_sync(0xffffffffu, bestv[i], off);
            int   oi = __shfl_xor_sync(0xffffffffu, besti[i], off);
            if (ov < bestv[i] || (ov == bestv[i] && oi < besti[i])) {
                bestv[i] = ov; besti[i] = oi;
            }
        }
    }

    if (tx == 0) {
        float lsum = 0.f;
        #pragma unroll
        for (int i = 0; i < 8; i++) {
            int m = ty * 8 + i;
            int n = n0 + m;
            g_idx[n] = besti[i];
            atomicAdd(&g_cnt[besti[i]], 1);
            lsum += sxsq[m] + bestv[i];   // ||x||^2 + (||w||^2 - 2 x.w)
        }
        atomicAdd(&s_loss, lsum);
    }
    __syncthreads();
    if (tid == 0) atomicAdd(&g_loss, (double)s_loss);
}

// ============================================================
// out: gather codebook rows back to BCHW, float4 per thread
// ============================================================
__global__ void out_kernel(const float* __restrict__ w, float* __restrict__ out) {
    int i = blockIdx.x * blockDim.x + threadIdx.x;  // over 8388608/4
    int hw = i & 1023;
    int c4 = (i >> 10) & 63;
    int b  = i >> 16;
    int n  = (b << 10) | hw;
    int idx = g_idx[n];
    float4 v = *(const float4*)&w[(size_t)idx * D_DIM + c4 * 4];
    size_t base = (size_t)b * CHW + (size_t)(c4 * 4) * HW + hw;
    out[base]            = v.x;
    out[base + HW]       = v.y;
    out[base + 2 * HW]   = v.z;
    out[base + 3 * HW]   = v.w;
}

// ============================================================
// one-hot scatter (region pre-zeroed by memset)
// ============================================================
__global__ void scat_kernel(float* __restrict__ enc) {
    int n = blockIdx.x * blockDim.x + threadIdx.x;
    enc[(size_t)n * K_CB + g_idx[n]] = 1.0f;
}

// ============================================================
// finalize: loss + entropy scalars
// ============================================================
__global__ void fin_kernel(float* __restrict__ scal) {
    __shared__ float red[32];
    int k = threadIdx.x;
    float p = (float)g_cnt[k] / (float)N_TOK;
    float t = -p * logf(p + 1e-10f);
    #pragma unroll
    for (int o = 16; o; o >>= 1) t += __shfl_xor_sync(0xffffffffu, t, o);
    if ((k & 31) == 0) red[k >> 5] = t;
    __syncthreads();
    if (k == 0) {
        float e = 0.f;
        #pragma unroll
        for (int i = 0; i < 32; i++) e += red[i];
        double mean = g_loss / ((double)N_TOK * (double)D_DIM);
        scal[0] = (float)(0.25 * mean);
        scal[1] = e;
    }
}

// ============================================================
extern "C" void kernel_launch(void* const* d_in, const int* in_sizes, int n_in,
                              void* d_out, int out_size) {
    const float* x = (const float*)d_in[0];   // [32,256,32,32]
    const float* w = (const float*)d_in[1];   // [1024,256]
    float* out = (float*)d_out;

    // layout: out (8388608) | loss (1) | entropy (1) | encodings (33554432)
    size_t enc_off  = (size_t)out_size - (size_t)N_TOK * K_CB;
    size_t scal_off = enc_off - 2;
    float* scal = out + scal_off;
    float* enc  = out + enc_off;

    cudaFuncSetAttribute(vq_main_kernel,
                         cudaFuncAttributeMaxDynamicSharedMemorySize, SMEM_BYTES);

    prep_kernel<<<K_CB, D_DIM>>>(w);
    cudaMemsetAsync(enc, 0, (size_t)N_TOK * K_CB * sizeof(float));
    vq_main_kernel<<<N_TOK / TM, 256, SMEM_BYTES>>>(x);
    out_kernel<<<(8388608 / 4) / 256, 256>>>(w, out);
    scat_kernel<<<N_TOK / 256, 256>>>(enc);
    fin_kernel<<<1, K_CB>>>(scal);
}

// round 5
// speedup vs baseline: 1.5118x; 1.3115x over previous
#include <cuda_runtime.h>
#include <cuda_bf16.h>
#include <math.h>
#include <stdint.h>

#define N_TOK 32768
#define K_CB  1024
#define D_DIM 256
#define HW    1024
#define CHW   (256*1024)

#define TM 128                 // tokens per CTA
#define A_ROW_B 528            // padded row bytes (256 bf16 = 512B + 16B pad)
#define A_SPLIT_B (128 * A_ROW_B)          // 67584
#define A_BYTES (3 * A_SPLIT_B)            // 202752
#define DYN_SMEM (A_BYTES + 4096 + 512 + 4096)   // + wsq + xsq + best

// ---------------- PTX helpers (plain sm_103-legal) ----------------
__device__ __forceinline__ uint32_t smem_u32(const void* p) {
    uint32_t a;
    asm("{ .reg .u64 t; cvta.to.shared.u64 t, %1; cvt.u32.u64 %0, t; }" : "=r"(a) : "l"(p));
    return a;
}

#define LDSM4(a, addr) \
    asm volatile("ldmatrix.sync.aligned.m8n8.x4.shared.b16 {%0,%1,%2,%3}, [%4];" \
        : "=r"((a)[0]), "=r"((a)[1]), "=r"((a)[2]), "=r"((a)[3]) : "r"(addr))

#define MMA16816(c, a, b0, b1) \
    asm volatile("mma.sync.aligned.m16n8k16.row.col.f32.bf16.bf16.f32 " \
        "{%0,%1,%2,%3}, {%4,%5,%6,%7}, {%8,%9}, {%0,%1,%2,%3};" \
        : "+f"((c)[0]), "+f"((c)[1]), "+f"((c)[2]), "+f"((c)[3]) \
        : "r"((a)[0]), "r"((a)[1]), "r"((a)[2]), "r"((a)[3]), "r"(b0), "r"(b1))

__device__ __forceinline__ void split3(float v, unsigned short& o1,
                                       unsigned short& o2, unsigned short& o3) {
    __nv_bfloat16 b1 = __float2bfloat16(v);
    float r1 = v - __bfloat162float(b1);
    __nv_bfloat16 b2 = __float2bfloat16(r1);
    float r2 = r1 - __bfloat162float(b2);
    __nv_bfloat16 b3 = __float2bfloat16(r2);
    o1 = __bfloat16_as_ushort(b1);
    o2 = __bfloat16_as_ushort(b2);
    o3 = __bfloat16_as_ushort(b3);
}

// ---- scratch (device globals) ----
// B image: [group g(64)][kk(16)][split(3)] x 512B (one warp's two n8-frags, per lane 16B)
__device__ uint8_t g_bimg[64 * 16 * 3 * 512];
__device__ float   g_wsq[K_CB];
__device__ int     g_idx[N_TOK];
__device__ int     g_cnt[K_CB];
__device__ double  g_loss;

// ============================================================
// prep: split W to bf16 triple in mma-B-fragment layout; ||w||^2
//   grid = 1024 (code k), block = 256 (dim d)
// ============================================================
__global__ void prep_kernel(const float* __restrict__ w) {
    int k = blockIdx.x;
    int d = threadIdx.x;
    float v = w[k * D_DIM + d];

    unsigned short a1, a2, a3;
    split3(v, a1, a2, a3);

    // m16n8k16 B fragment mapping: lane = gid*4+tg holds col n=gid(+8 in regs 2,3),
    // rows k = tg*2, tg*2+1 (reg lo) and tg*2+8, tg*2+9 (reg hi)
    int g = k >> 4, nl = k & 15, kk = d >> 4, kl = d & 15;
    int lane = (nl & 7) * 4 + ((kl & 7) >> 1);
    int reg  = ((nl >> 3) << 1) | (kl >> 3);
    size_t base = ((size_t)(g * 16 + kk) * 3) * 512 + (size_t)lane * 16 + reg * 4 + (kl & 1) * 2;
    *(unsigned short*)(g_bimg + base + 0 * 512) = a1;
    *(unsigned short*)(g_bimg + base + 1 * 512) = a2;
    *(unsigned short*)(g_bimg + base + 2 * 512) = a3;

    float s = v * v;
    __shared__ float red[8];
    #pragma unroll
    for (int o = 16; o; o >>= 1) s += __shfl_xor_sync(0xffffffffu, s, o);
    if ((d & 31) == 0) red[d >> 5] = s;
    __syncthreads();
    if (d == 0) {
        float t = 0.f;
        #pragma unroll
        for (int i = 0; i < 8; i++) t += red[i];
        g_wsq[k] = t;
    }
    if (blockIdx.x == 0) {
        for (int i = d; i < K_CB; i += blockDim.x) g_cnt[i] = 0;
        if (d == 0) g_loss = 0.0;
    }
}

// ============================================================
// main: bf16 3-way-split mma.sync GEMM + fused argmin
//   grid 256, block 256 (8 warps: wm in {0,1} x wn in {0..3})
//   warp tile: 64 rows x 32 codes per iteration, 8 iterations
// ============================================================
extern __shared__ uint8_t dynsm[];
__global__ void __launch_bounds__(256, 1) vq_main_kernel(const float* __restrict__ x) {
    float* s_wsq  = (float*)(dynsm + A_BYTES);
    float* s_xsq  = (float*)(dynsm + A_BYTES + 4096);
    uint2* s_best = (uint2*)(dynsm + A_BYTES + 4608);

    const int tid  = threadIdx.x;
    const int lane = tid & 31, wid = tid >> 5;
    const int wm = wid >> 2, wn = wid & 3;
    const int tg = lane & 3, gid = lane >> 2;

    // ---------- phase 1: load X, 3-way split into smem; ||x||^2; stage wsq ----------
    if (tid < 128) s_xsq[tid] = 0.f;
    for (int i = tid; i < K_CB; i += 256) s_wsq[i] = g_wsq[i];
    __syncthreads();
    {
        const int m = tid & 127;
        const int dbase = (tid >> 7) * 128;     // 0 or 128
        const int n = blockIdx.x * TM + m;
        const int b = n >> 10, hw = n & 1023;
        const float* px = x + (size_t)b * CHW + (size_t)dbase * HW + hw;
        uint8_t* arow = dynsm + (size_t)m * A_ROW_B + (size_t)dbase * 2;
        float xs = 0.f;
        #pragma unroll 8
        for (int i = 0; i < 128; ++i) {
            float v = px[(size_t)i * HW];
            xs = fmaf(v, v, xs);
            unsigned short e1, e2, e3;
            split3(v, e1, e2, e3);
            *(unsigned short*)(arow + 0 * A_SPLIT_B + i * 2) = e1;
            *(unsigned short*)(arow + 1 * A_SPLIT_B + i * 2) = e2;
            *(unsigned short*)(arow + 2 * A_SPLIT_B + i * 2) = e3;
        }
        atomicAdd(&s_xsq[m], xs);
    }
    __syncthreads();

    // ---------- phase 2: GEMM + argmin ----------
    // ldmatrix lane address: rows 0-15 (lane&15), col half (lane>>4)*16B
    const uint32_t aB = smem_u32(dynsm)
                      + (uint32_t)(wm * 64 + (lane & 15)) * A_ROW_B
                      + (uint32_t)(lane >> 4) * 16;
    const uint8_t* bLane = g_bimg + (size_t)lane * 16;

    float bestv[8];
    int   besti[8];
    #pragma unroll
    for (int s = 0; s < 8; s++) { bestv[s] = 3.4e38f; besti[s] = 0; }

    for (int it = 0; it < 8; ++it) {
        const int g0 = (it * 4 + wn) * 2;            // first 16-code group
        const uint8_t* bIt = bLane + (size_t)g0 * 24576;   // 16*3*512 per group

        float acc[4][4][4];
        #pragma unroll
        for (int t = 0; t < 4; t++)
            #pragma unroll
            for (int f = 0; f < 4; f++)
                #pragma unroll
                for (int r = 0; r < 4; r++) acc[t][f][r] = 0.f;

        #pragma unroll 2
        for (int kk = 0; kk < 16; ++kk) {
            uint4 bf[2][3];
            #pragma unroll
            for (int grp = 0; grp < 2; ++grp)
                #pragma unroll
                for (int s = 0; s < 3; ++s)
                    bf[grp][s] = *(const uint4*)(bIt + grp * 24576 + (kk * 3 + s) * 512);

            #pragma unroll
            for (int sa = 0; sa < 3; ++sa) {
                uint32_t af[4][4];
                #pragma unroll
                for (int t = 0; t < 4; ++t)
                    LDSM4(af[t], aB + sa * A_SPLIT_B + t * (16 * A_ROW_B) + kk * 32);
                #pragma unroll
                for (int sb = 0; sb < 3; ++sb) {
                    if (sa + sb > 2) continue;       // pairs: 11,12,21,22,13,31
                    #pragma unroll
                    for (int t = 0; t < 4; ++t) {
                        MMA16816(acc[t][0], af[t], bf[0][sb].x, bf[0][sb].y);
                        MMA16816(acc[t][1], af[t], bf[0][sb].z, bf[0][sb].w);
                        MMA16816(acc[t][2], af[t], bf[1][sb].x, bf[1][sb].y);
                        MMA16816(acc[t][3], af[t], bf[1][sb].z, bf[1][sb].w);
                    }
                }
            }
        }

        // epilogue: score = ||w||^2 - 2 x.w, running argmin (ascending code order)
        #pragma unroll
        for (int t = 0; t < 4; ++t)
            #pragma unroll
            for (int f = 0; f < 4; ++f) {
                const int cb = g0 * 16 + (f >> 1) * 16 + (f & 1) * 8 + tg * 2;
                #pragma unroll
                for (int r = 0; r < 4; ++r) {
                    const int code = cb + (r & 1);
                    const float sc = fmaf(-2.f, acc[t][f][r], s_wsq[code]);
                    const int slot = t * 2 + (r >> 1);
                    if (sc < bestv[slot]) { bestv[slot] = sc; besti[slot] = code; }
                }
            }
    }

    // ---------- reduce: across tg lanes (cols), then across wn warps ----------
    #pragma unroll
    for (int slot = 0; slot < 8; ++slot) {
        #pragma unroll
        for (int off = 1; off <= 2; off <<= 1) {
            float ov = __shfl_xor_sync(0xffffffffu, bestv[slot], off);
            int   oi = __shfl_xor_sync(0xffffffffu, besti[slot], off);
            if (ov < bestv[slot] || (ov == bestv[slot] && oi < besti[slot])) {
                bestv[slot] = ov; besti[slot] = oi;
            }
        }
    }
    if (tg == 0) {
        #pragma unroll
        for (int slot = 0; slot < 8; ++slot) {
            int row = wm * 64 + (slot >> 1) * 16 + (slot & 1) * 8 + gid;
            s_best[row * 4 + wn] = make_uint2(__float_as_uint(bestv[slot]),
                                             (uint32_t)besti[slot]);
        }
    }
    __syncthreads();

    if (tid < 128) {
        float bv = 3.4e38f; int bi = 0;
        #pragma unroll
        for (int w = 0; w < 4; ++w) {
            uint2 e = s_best[tid * 4 + w];
            float v = __uint_as_float(e.x);
            int   i = (int)e.y;
            if (v < bv || (v == bv && i < bi)) { bv = v; bi = i; }
        }
        const int n = blockIdx.x * TM + tid;
        g_idx[n] = bi;
        atomicAdd(&g_cnt[bi], 1);
        float ls = s_xsq[tid] + bv;          // ||x||^2 + (||w||^2 - 2 x.w)
        #pragma unroll
        for (int o = 16; o; o >>= 1) ls += __shfl_xor_sync(0xffffffffu, ls, o);
        if (lane == 0) atomicAdd(&g_loss, (double)ls);
    }
}

// ============================================================
// out: gather codebook rows back to BCHW
// ============================================================
__global__ void out_kernel(const float* __restrict__ w, float* __restrict__ out) {
    int i = blockIdx.x * blockDim.x + threadIdx.x;
    int hw = i & 1023;
    int c4 = (i >> 10) & 63;
    int b  = i >> 16;
    int n  = (b << 10) | hw;
    int idx = g_idx[n];
    float4 v = *(const float4*)&w[(size_t)idx * D_DIM + c4 * 4];
    size_t base = (size_t)b * CHW + (size_t)(c4 * 4) * HW + hw;
    out[base]          = v.x;
    out[base + HW]     = v.y;
    out[base + 2 * HW] = v.z;
    out[base + 3 * HW] = v.w;
}

__global__ void scat_kernel(float* __restrict__ enc) {
    int n = blockIdx.x * blockDim.x + threadIdx.x;
    enc[(size_t)n * K_CB + g_idx[n]] = 1.0f;
}

__global__ void fin_kernel(float* __restrict__ scal) {
    __shared__ float red[32];
    int k = threadIdx.x;
    float p = (float)g_cnt[k] / (float)N_TOK;
    float t = -p * logf(p + 1e-10f);
    #pragma unroll
    for (int o = 16; o; o >>= 1) t += __shfl_xor_sync(0xffffffffu, t, o);
    if ((k & 31) == 0) red[k >> 5] = t;
    __syncthreads();
    if (k == 0) {
        float e = 0.f;
        #pragma unroll
        for (int i = 0; i < 32; i++) e += red[i];
        double mean = g_loss / ((double)N_TOK * (double)D_DIM);
        scal[0] = (float)(0.25 * mean);
        scal[1] = e;
    }
}

// ============================================================
extern "C" void kernel_launch(void* const* d_in, const int* in_sizes, int n_in,
                              void* d_out, int out_size) {
    const float* x = (const float*)d_in[0];   // [32,256,32,32]
    const float* w = (const float*)d_in[1];   // [1024,256]
    float* out = (float*)d_out;

    size_t enc_off  = (size_t)out_size - (size_t)N_TOK * K_CB;
    size_t scal_off = enc_off - 2;
    float* scal = out + scal_off;
    float* enc  = out + enc_off;

    cudaFuncSetAttribute(vq_main_kernel,
                         cudaFuncAttributeMaxDynamicSharedMemorySize, DYN_SMEM);

    prep_kernel<<<K_CB, D_DIM>>>(w);
    cudaMemsetAsync(enc, 0, (size_t)N_TOK * K_CB * sizeof(float));
    vq_main_kernel<<<N_TOK / TM, 256, DYN_SMEM>>>(x);
    out_kernel<<<(8388608 / 4) / 256, 256>>>(w, out);
    scat_kernel<<<N_TOK / 256, 256>>>(enc);
    fin_kernel<<<1, K_CB>>>(scal);
}